// round 3
// baseline (speedup 1.0000x reference)
#include <cuda_runtime.h>
#include <math.h>

#define FULLMASK 0xffffffffu
#define EPS_REC 1e-4f

// ---------------------------------------------------------------------------
// Warp-parallel Cholesky test on C = M - eps*I. Lane j owns column j.
// Returns warp-uniform true iff lambda_min > eps (ReEig is identity).
// ---------------------------------------------------------------------------
template<int NR>
__device__ __forceinline__ bool chol_test(const float (&m)[20], int lane)
{
    float c[NR];
    #pragma unroll
    for (int k = 0; k < NR; ++k) c[k] = (lane == k) ? (m[k] - EPS_REC) : m[k];

    bool ok = true;
    #pragma unroll
    for (int k = 0; k < NR; ++k) {
        float ckk = __shfl_sync(FULLMASK, c[k], k);
        if (ckk <= 1e-12f) { ok = false; break; }
        float inv  = __fdividef(1.0f, ckk);
        float gmul = c[k] * inv;
        #pragma unroll
        for (int i = k + 1; i < NR; ++i) {
            float pk = __shfl_sync(FULLMASK, c[i], k);
            c[i] = fmaf(-pk, gmul, c[i]);
        }
    }
    return ok;
}

// ---------------------------------------------------------------------------
// One-sided Jacobi (padded [20] arrays) — cold fallback path only.
// ---------------------------------------------------------------------------
template<int N>
__device__ __forceinline__ void jacobi_onesided(float (&g)[20], float (&v)[20],
                                                int lane, int max_sweeps)
{
    constexpr int M = N - 1;
    #pragma unroll
    for (int k = 0; k < N; ++k) v[k] = (lane == k) ? 1.0f : 0.0f;

    for (int sweep = 0; sweep < max_sweeps; ++sweep) {
        bool anyrot = false;
        for (int r = 0; r < M; ++r) {
            int partner;
            if (lane >= N)      partner = lane;
            else if (lane == M) partner = r;
            else if (lane == r) partner = M;
            else                partner = ((2 * r - lane) % M + M) % M;

            float pg[N];
            float a0 = 0.f, a1 = 0.f, a2 = 0.f, a3 = 0.f;
            float d0 = 0.f, d1 = 0.f, d2 = 0.f, d3 = 0.f;
            #pragma unroll
            for (int k = 0; k < N; ++k) {
                pg[k] = __shfl_sync(FULLMASK, g[k], partner);
                switch (k & 3) {
                    case 0: a0 = fmaf(g[k], g[k], a0); d0 = fmaf(g[k], pg[k], d0); break;
                    case 1: a1 = fmaf(g[k], g[k], a1); d1 = fmaf(g[k], pg[k], d1); break;
                    case 2: a2 = fmaf(g[k], g[k], a2); d2 = fmaf(g[k], pg[k], d2); break;
                    default:a3 = fmaf(g[k], g[k], a3); d3 = fmaf(g[k], pg[k], d3); break;
                }
            }
            float a = (a0 + a1) + (a2 + a3);
            float d = (d0 + d1) + (d2 + d3);
            float bb = __shfl_sync(FULLMASK, a, partner);
            bool  lower = lane < partner;
            float app = lower ? a  : bb;
            float aqq = lower ? bb : a;

            bool rot = (d * d > 1e-12f * app * aqq);
            anyrot |= rot;

            float dsafe = rot ? d : 1.0f;
            float tau = __fdividef(aqq - app, 2.0f * dsafe);
            float t   = __fdividef(copysignf(1.0f, tau),
                                   fabsf(tau) + __fsqrt_rn(fmaf(tau, tau, 1.0f)));
            float cc  = __frsqrt_rn(fmaf(t, t, 1.0f));
            float ss  = t * cc;
            if (!rot) { cc = 1.0f; ss = 0.0f; }
            float sl = lower ? -ss : ss;

            #pragma unroll
            for (int k = 0; k < N; ++k) {
                float pv = __shfl_sync(FULLMASK, v[k], partner);
                g[k] = fmaf(sl, pg[k], cc * g[k]);
                v[k] = fmaf(sl, pv,    cc * v[k]);
            }
        }
        if (!__any_sync(FULLMASK, anyrot)) break;
    }
}

// Dedicated 4x4 one-sided Jacobi (hot: LogEig stage).
__device__ __forceinline__ void jacobi4(float (&g)[4], float (&v)[4],
                                        int lane, int max_sweeps)
{
    #pragma unroll
    for (int k = 0; k < 4; ++k) v[k] = (lane == k) ? 1.0f : 0.0f;

    for (int sweep = 0; sweep < max_sweeps; ++sweep) {
        bool anyrot = false;
        #pragma unroll
        for (int r = 0; r < 3; ++r) {
            int partner;
            if (lane >= 4)      partner = lane;
            else if (lane == 3) partner = r;
            else if (lane == r) partner = 3;
            else                partner = ((2 * r - lane) % 3 + 3) % 3;

            float pg[4];
            float a = 0.f, d = 0.f;
            #pragma unroll
            for (int k = 0; k < 4; ++k) {
                pg[k] = __shfl_sync(FULLMASK, g[k], partner);
                a = fmaf(g[k], g[k], a);
                d = fmaf(g[k], pg[k], d);
            }
            float bb = __shfl_sync(FULLMASK, a, partner);
            bool  lower = lane < partner;
            float app = lower ? a  : bb;
            float aqq = lower ? bb : a;

            bool rot = (d * d > 1e-12f * app * aqq);
            anyrot |= rot;

            float dsafe = rot ? d : 1.0f;
            float tau = __fdividef(aqq - app, 2.0f * dsafe);
            float t   = __fdividef(copysignf(1.0f, tau),
                                   fabsf(tau) + __fsqrt_rn(fmaf(tau, tau, 1.0f)));
            float cc  = __frsqrt_rn(fmaf(t, t, 1.0f));
            float ss  = t * cc;
            if (!rot) { cc = 1.0f; ss = 0.0f; }
            float sl = lower ? -ss : ss;

            #pragma unroll
            for (int k = 0; k < 4; ++k) {
                float pv = __shfl_sync(FULLMASK, v[k], partner);
                g[k] = fmaf(sl, pg[k], cc * g[k]);
                v[k] = fmaf(sl, pv,    cc * v[k]);
            }
        }
        if (!__any_sync(FULLMASK, anyrot)) break;
    }
}

// ReEig correction: m += (eps - lambda_i) v_i v_i^T over deficient pairs.
template<int N, int NREAL>
__device__ __forceinline__ void reeig_correction(float (&m)[20], const float (&g)[20],
                                                 const float (&v)[20], int lane)
{
    float lam = 0.f;
    #pragma unroll
    for (int k = 0; k < N; ++k) lam = fmaf(v[k], g[k], lam);

    bool defic = (lane < NREAL) && (lam < EPS_REC);
    unsigned mask = __ballot_sync(FULLMASK, defic);
    while (mask) {
        int i = __ffs(mask) - 1;
        mask &= mask - 1;
        float li   = __shfl_sync(FULLMASK, lam, i);
        float coef = EPS_REC - li;
        float vmy  = 0.f;
        float bv[N];
        #pragma unroll
        for (int k = 0; k < N; ++k) {
            bv[k] = __shfl_sync(FULLMASK, v[k], i);
            vmy   = (lane == k) ? bv[k] : vmy;
        }
        float cf = coef * vmy;
        #pragma unroll
        for (int k = 0; k < N; ++k) m[k] = fmaf(cf, bv[k], m[k]);
    }
}

// Vectorized dot of a 16B-aligned shared row (Q float4s) with a register array.
template<int Q>
__device__ __forceinline__ float dotv(const float* __restrict__ row,
                                      const float (&w)[20])
{
    const float4* r4 = (const float4*)row;
    float a0 = 0.f, a1 = 0.f, a2 = 0.f, a3 = 0.f;
    #pragma unroll
    for (int q = 0; q < Q; ++q) {
        float4 rv = r4[q];
        a0 = fmaf(rv.x, w[4 * q + 0], a0);
        a1 = fmaf(rv.y, w[4 * q + 1], a1);
        a2 = fmaf(rv.z, w[4 * q + 2], a2);
        a3 = fmaf(rv.w, w[4 * q + 3], a3);
    }
    return (a0 + a1) + (a2 + a3);
}

// ---------------------------------------------------------------------------
// One warp per batch element; 8 warps per 256-thread block.
// Sm rows padded to 20 floats (80B, 16B-aligned) for LDS.128.
// ---------------------------------------------------------------------------
__global__ void __launch_bounds__(256, 2)
spd_net_kernel(const float* __restrict__ x,
               const float* __restrict__ w1,
               const float* __restrict__ w2,
               const float* __restrict__ w3,
               const float* __restrict__ fcw,
               float* __restrict__ out_logp,
               float* __restrict__ out_feat,
               int B)
{
    __shared__ float sw1[361];            // w1 row-major (for lane columns)
    __shared__ float sw2[304];            // w2 row-major
    __shared__ float sw3[64];             // w3 row-major
    __shared__ float sw1t[19][20];        // w1^T, rows padded + zeroed
    __shared__ float sw2t[16][20];        // w2^T
    __shared__ float sw3t[4][16];         // w3^T
    __shared__ float sfc[32];
    __shared__ __align__(16) float S[8][20][20];

    int tid = threadIdx.x;
    for (int i = tid; i < 361; i += 256) sw1[i] = w1[i];
    for (int i = tid; i < 304; i += 256) sw2[i] = w2[i];
    if (tid < 64) sw3[tid] = w3[tid];
    if (tid < 32) sfc[tid] = fcw[tid];
    for (int idx = tid; idx < 19 * 20; idx += 256) {
        int i = idx / 20, k = idx % 20;
        sw1t[i][k] = (k < 19) ? w1[k * 19 + i] : 0.f;
    }
    for (int idx = tid; idx < 16 * 20; idx += 256) {
        int i = idx / 20, k = idx % 20;
        sw2t[i][k] = (k < 19) ? w2[k * 16 + i] : 0.f;
    }
    if (tid < 64) sw3t[tid / 16][tid % 16] = w3[(tid % 16) * 4 + tid / 16];
    __syncthreads();

    int warp = tid >> 5, lane = tid & 31;
    int b = blockIdx.x * 8 + warp;
    if (b >= B) return;
    float (*Sm)[20] = S[warp];

    // load X (19x19) into padded rows; zero the pad column
    const float* xb = x + (size_t)b * 361;
    for (int i = lane; i < 361; i += 32) Sm[i / 19][i % 19] = xb[i];
    if (lane < 20) Sm[lane][19] = 0.f;
    __syncwarp();

    float m[20], t[20], wc[20];

    // ---- stage 1: M1 = w1^T X w1 (column `lane`) ----
    {
        int j = (lane < 19) ? lane : 0;
        #pragma unroll
        for (int k = 0; k < 19; ++k) wc[k] = sw1[k * 19 + j];
        wc[19] = 0.f;
        #pragma unroll
        for (int i = 0; i < 19; ++i) t[i] = dotv<5>(Sm[i], wc);
        t[19] = 0.f;
        #pragma unroll
        for (int i = 0; i < 19; ++i) {
            float acc = dotv<5>(sw1t[i], t);
            m[i] = (lane < 19) ? acc : 0.f;
        }
        m[19] = 0.f;
    }

    // ---- stage 2: ReEig(19x19) — Cholesky fast path ----
    if (!chol_test<19>(m, lane)) {
        float g[20], v[20];
        #pragma unroll
        for (int k = 0; k < 20; ++k) g[k] = m[k];
        jacobi_onesided<20>(g, v, lane, 12);
        reeig_correction<20, 19>(m, g, v, lane);
    }

    __syncwarp();
    if (lane < 19) {
        #pragma unroll
        for (int k = 0; k < 19; ++k) Sm[k][lane] = m[k];   // Y1 (pad col stays 0)
    }
    __syncwarp();

    // ---- stage 3: M2 = w2^T Y1 w2 (16x16) ----
    {
        int j = (lane < 16) ? lane : 0;
        #pragma unroll
        for (int k = 0; k < 19; ++k) wc[k] = sw2[k * 16 + j];
        wc[19] = 0.f;
        #pragma unroll
        for (int kk = 0; kk < 19; ++kk) t[kk] = dotv<5>(Sm[kk], wc);
        t[19] = 0.f;
        #pragma unroll
        for (int i = 0; i < 16; ++i) {
            float acc = dotv<5>(sw2t[i], t);
            m[i] = (lane < 16) ? acc : 0.f;
        }
        #pragma unroll
        for (int i = 16; i < 20; ++i) m[i] = 0.f;
    }

    // ---- stage 4: ReEig(16x16) — Cholesky fast path ----
    if (!chol_test<16>(m, lane)) {
        float g[20], v[20];
        #pragma unroll
        for (int k = 0; k < 20; ++k) g[k] = m[k];
        jacobi_onesided<16>(g, v, lane, 12);
        reeig_correction<16, 16>(m, g, v, lane);
    }

    __syncwarp();
    if (lane < 16) {
        #pragma unroll
        for (int k = 0; k < 16; ++k) Sm[k][lane] = m[k];   // Y2
    }
    __syncwarp();

    // ---- stage 5: M3 = w3^T Y2 w3 (4x4) ----
    float m4[4];
    {
        int j = (lane < 4) ? lane : 0;
        #pragma unroll
        for (int k = 0; k < 16; ++k) wc[k] = sw3[k * 4 + j];
        #pragma unroll
        for (int k = 16; k < 20; ++k) wc[k] = 0.f;
        #pragma unroll
        for (int kk = 0; kk < 16; ++kk) t[kk] = dotv<4>(Sm[kk], wc);
        #pragma unroll
        for (int kk = 16; kk < 20; ++kk) t[kk] = 0.f;
        #pragma unroll
        for (int i = 0; i < 4; ++i) {
            float acc = dotv<4>(sw3t[i], t);
            m4[i] = (lane < 4) ? acc : 0.f;
        }
    }

    // ---- stage 6: LogEig(4x4) ----
    float g4[4], v4[4];
    #pragma unroll
    for (int k = 0; k < 4; ++k) g4[k] = m4[k];
    jacobi4(g4, v4, lane, 10);

    float lam = 0.f;
    #pragma unroll
    for (int k = 0; k < 4; ++k) lam = fmaf(v4[k], g4[k], lam);
    float ll = logf(fmaxf(lam, 1e-30f));

    float c3[4] = {0.f, 0.f, 0.f, 0.f};
    #pragma unroll
    for (int mm = 0; mm < 4; ++mm) {
        float llm = __shfl_sync(FULLMASK, ll,  mm);
        float bv0 = __shfl_sync(FULLMASK, v4[0], mm);
        float bv1 = __shfl_sync(FULLMASK, v4[1], mm);
        float bv2 = __shfl_sync(FULLMASK, v4[2], mm);
        float bv3 = __shfl_sync(FULLMASK, v4[3], mm);
        float vmj = (lane == 0) ? bv0 : (lane == 1) ? bv1 : (lane == 2) ? bv2 : bv3;
        float cf  = llm * vmj;
        c3[0] = fmaf(cf, bv0, c3[0]);
        c3[1] = fmaf(cf, bv1, c3[1]);
        c3[2] = fmaf(cf, bv2, c3[2]);
        c3[3] = fmaf(cf, bv3, c3[3]);
    }
    if (lane >= 4) { c3[0] = c3[1] = c3[2] = c3[3] = 0.f; }

    if (out_feat && lane < 4) {
        #pragma unroll
        for (int i = 0; i < 4; ++i)
            out_feat[(size_t)b * 16 + i * 4 + lane] = c3[i];
    }

    if (out_logp) {
        float p0 = 0.f, p1 = 0.f;
        int jj = (lane < 4) ? lane : 0;
        #pragma unroll
        for (int i = 0; i < 4; ++i) {
            int f = i * 4 + jj;
            p0 = fmaf(c3[i], sfc[f * 2 + 0], p0);
            p1 = fmaf(c3[i], sfc[f * 2 + 1], p1);
        }
        p0 += __shfl_xor_sync(FULLMASK, p0, 1);
        p0 += __shfl_xor_sync(FULLMASK, p0, 2);
        p1 += __shfl_xor_sync(FULLMASK, p1, 1);
        p1 += __shfl_xor_sync(FULLMASK, p1, 2);
        if (lane == 0) {
            float mx  = fmaxf(p0, p1);
            float lse = mx + logf(expf(p0 - mx) + expf(p1 - mx));
            out_logp[(size_t)b * 2 + 0] = p0 - lse;
            out_logp[(size_t)b * 2 + 1] = p1 - lse;
        }
    }
}

extern "C" void kernel_launch(void* const* d_in, const int* in_sizes, int n_in,
                              void* d_out, int out_size)
{
    const float* x   = (const float*)d_in[0];
    const float* w1  = (const float*)d_in[1];
    const float* w2  = (const float*)d_in[2];
    const float* w3  = (const float*)d_in[3];
    const float* fcw = (const float*)d_in[4];
    int B = in_sizes[0] / 361;

    float* out  = (float*)d_out;
    float* logp = nullptr;
    float* feat = nullptr;
    if (out_size == 18 * B)      { logp = out; feat = out + (size_t)2 * B; }
    else if (out_size == 2 * B)  { logp = out; }
    else if (out_size == 16 * B) { feat = out; }
    else                         { logp = out; feat = out + (size_t)2 * B; }

    int blocks = (B + 7) / 8;
    spd_net_kernel<<<blocks, 256>>>(x, w1, w2, w3, fcw, logp, feat, B);
}

// round 4
// speedup vs baseline: 1.1417x; 1.1417x over previous
#include <cuda_runtime.h>
#include <math.h>

#define FULLMASK 0xffffffffu
#define EPS_REC 1e-4f

// ---------------------------------------------------------------------------
// Warp-parallel Cholesky test on C = M - eps*I. Lane j owns column j.
// Returns warp-uniform true iff lambda_min > eps (ReEig is identity).
// ---------------------------------------------------------------------------
template<int NR>
__device__ __forceinline__ bool chol_test(const float (&m)[20], int lane)
{
    float c[NR];
    #pragma unroll
    for (int k = 0; k < NR; ++k) c[k] = (lane == k) ? (m[k] - EPS_REC) : m[k];

    bool ok = true;
    #pragma unroll
    for (int k = 0; k < NR; ++k) {
        float ckk = __shfl_sync(FULLMASK, c[k], k);
        if (ckk <= 1e-12f) { ok = false; break; }
        float inv  = __fdividef(1.0f, ckk);
        float gmul = c[k] * inv;
        #pragma unroll
        for (int i = k + 1; i < NR; ++i) {
            float pk = __shfl_sync(FULLMASK, c[i], k);
            c[i] = fmaf(-pk, gmul, c[i]);
        }
    }
    return ok;
}

// ---------------------------------------------------------------------------
// One-sided Jacobi (padded [20] arrays) — COLD fallback path. Under the
// 85-reg launch-bounds budget ptxas spills this path to local; that is
// intentional (it essentially never executes).
// ---------------------------------------------------------------------------
template<int N>
__device__ void jacobi_onesided(float (&g)[20], float (&v)[20],
                                int lane, int max_sweeps)
{
    constexpr int M = N - 1;
    #pragma unroll
    for (int k = 0; k < N; ++k) v[k] = (lane == k) ? 1.0f : 0.0f;

    for (int sweep = 0; sweep < max_sweeps; ++sweep) {
        bool anyrot = false;
        for (int r = 0; r < M; ++r) {
            int partner;
            if (lane >= N)      partner = lane;
            else if (lane == M) partner = r;
            else if (lane == r) partner = M;
            else                partner = ((2 * r - lane) % M + M) % M;

            float pg[N];
            float a0 = 0.f, a1 = 0.f, d0 = 0.f, d1 = 0.f;
            #pragma unroll
            for (int k = 0; k < N; ++k) {
                pg[k] = __shfl_sync(FULLMASK, g[k], partner);
                if (k & 1) { a1 = fmaf(g[k], g[k], a1); d1 = fmaf(g[k], pg[k], d1); }
                else       { a0 = fmaf(g[k], g[k], a0); d0 = fmaf(g[k], pg[k], d0); }
            }
            float a = a0 + a1;
            float d = d0 + d1;
            float bb = __shfl_sync(FULLMASK, a, partner);
            bool  lower = lane < partner;
            float app = lower ? a  : bb;
            float aqq = lower ? bb : a;

            bool rot = (d * d > 1e-12f * app * aqq);
            anyrot |= rot;

            float dsafe = rot ? d : 1.0f;
            float tau = __fdividef(aqq - app, 2.0f * dsafe);
            float t   = __fdividef(copysignf(1.0f, tau),
                                   fabsf(tau) + __fsqrt_rn(fmaf(tau, tau, 1.0f)));
            float cc  = __frsqrt_rn(fmaf(t, t, 1.0f));
            float ss  = t * cc;
            if (!rot) { cc = 1.0f; ss = 0.0f; }
            float sl = lower ? -ss : ss;

            #pragma unroll
            for (int k = 0; k < N; ++k) {
                float pv = __shfl_sync(FULLMASK, v[k], partner);
                g[k] = fmaf(sl, pg[k], cc * g[k]);
                v[k] = fmaf(sl, pv,    cc * v[k]);
            }
        }
        if (!__any_sync(FULLMASK, anyrot)) break;
    }
}

// Dedicated 4x4 one-sided Jacobi (HOT: LogEig stage).
__device__ __forceinline__ void jacobi4(float (&g)[4], float (&v)[4],
                                        int lane, int max_sweeps)
{
    #pragma unroll
    for (int k = 0; k < 4; ++k) v[k] = (lane == k) ? 1.0f : 0.0f;

    for (int sweep = 0; sweep < max_sweeps; ++sweep) {
        bool anyrot = false;
        #pragma unroll
        for (int r = 0; r < 3; ++r) {
            int partner;
            if (lane >= 4)      partner = lane;
            else if (lane == 3) partner = r;
            else if (lane == r) partner = 3;
            else                partner = ((2 * r - lane) % 3 + 3) % 3;

            float pg[4];
            float a = 0.f, d = 0.f;
            #pragma unroll
            for (int k = 0; k < 4; ++k) {
                pg[k] = __shfl_sync(FULLMASK, g[k], partner);
                a = fmaf(g[k], g[k], a);
                d = fmaf(g[k], pg[k], d);
            }
            float bb = __shfl_sync(FULLMASK, a, partner);
            bool  lower = lane < partner;
            float app = lower ? a  : bb;
            float aqq = lower ? bb : a;

            bool rot = (d * d > 1e-12f * app * aqq);
            anyrot |= rot;

            float dsafe = rot ? d : 1.0f;
            float tau = __fdividef(aqq - app, 2.0f * dsafe);
            float t   = __fdividef(copysignf(1.0f, tau),
                                   fabsf(tau) + __fsqrt_rn(fmaf(tau, tau, 1.0f)));
            float cc  = __frsqrt_rn(fmaf(t, t, 1.0f));
            float ss  = t * cc;
            if (!rot) { cc = 1.0f; ss = 0.0f; }
            float sl = lower ? -ss : ss;

            #pragma unroll
            for (int k = 0; k < 4; ++k) {
                float pv = __shfl_sync(FULLMASK, v[k], partner);
                g[k] = fmaf(sl, pg[k], cc * g[k]);
                v[k] = fmaf(sl, pv,    cc * v[k]);
            }
        }
        if (!__any_sync(FULLMASK, anyrot)) break;
    }
}

// ReEig correction: m += (eps - lambda_i) v_i v_i^T over deficient pairs. (COLD)
template<int N, int NREAL>
__device__ void reeig_correction(float (&m)[20], const float (&g)[20],
                                 const float (&v)[20], int lane)
{
    float lam = 0.f;
    #pragma unroll
    for (int k = 0; k < N; ++k) lam = fmaf(v[k], g[k], lam);

    bool defic = (lane < NREAL) && (lam < EPS_REC);
    unsigned mask = __ballot_sync(FULLMASK, defic);
    while (mask) {
        int i = __ffs(mask) - 1;
        mask &= mask - 1;
        float li   = __shfl_sync(FULLMASK, lam, i);
        float coef = EPS_REC - li;
        float vmy  = 0.f;
        float bv[N];
        #pragma unroll
        for (int k = 0; k < N; ++k) {
            bv[k] = __shfl_sync(FULLMASK, v[k], i);
            vmy   = (lane == k) ? bv[k] : vmy;
        }
        float cf = coef * vmy;
        #pragma unroll
        for (int k = 0; k < N; ++k) m[k] = fmaf(cf, bv[k], m[k]);
    }
}

// Vectorized dot of a 16B-aligned shared row (Q float4s) with a register array.
template<int Q, int W>
__device__ __forceinline__ float dotv(const float* __restrict__ row,
                                      const float (&w)[W])
{
    const float4* r4 = (const float4*)row;
    float a0 = 0.f, a1 = 0.f, a2 = 0.f, a3 = 0.f;
    #pragma unroll
    for (int q = 0; q < Q; ++q) {
        float4 rv = r4[q];
        a0 = fmaf(rv.x, w[4 * q + 0], a0);
        a1 = fmaf(rv.y, w[4 * q + 1], a1);
        a2 = fmaf(rv.z, w[4 * q + 2], a2);
        a3 = fmaf(rv.w, w[4 * q + 3], a3);
    }
    return (a0 + a1) + (a2 + a3);
}

// ---------------------------------------------------------------------------
// One warp per batch element; 8 warps per 256-thread block.
// launch_bounds(256,3): 24 warps/SM, 85-reg budget (cold Jacobi spills).
// ---------------------------------------------------------------------------
__global__ void __launch_bounds__(256, 3)
spd_net_kernel(const float* __restrict__ x,
               const float* __restrict__ w1,
               const float* __restrict__ w2,
               const float* __restrict__ w3,
               const float* __restrict__ fcw,
               float* __restrict__ out_logp,
               float* __restrict__ out_feat,
               int B)
{
    __shared__ float sw1[361];            // w1 row-major (lane columns)
    __shared__ float sw2[304];            // w2 row-major
    __shared__ float sw3[64];             // w3 row-major
    __shared__ __align__(16) float sw1t[19][20];   // w1^T, padded + zeroed
    __shared__ __align__(16) float sw2t[16][20];   // w2^T
    __shared__ __align__(16) float sw3t[4][16];    // w3^T
    __shared__ float sfc[32];
    __shared__ __align__(16) float S[8][20][20];

    int tid = threadIdx.x;
    for (int i = tid; i < 361; i += 256) sw1[i] = w1[i];
    for (int i = tid; i < 304; i += 256) sw2[i] = w2[i];
    if (tid < 64) sw3[tid] = w3[tid];
    if (tid < 32) sfc[tid] = fcw[tid];
    for (int idx = tid; idx < 19 * 20; idx += 256) {
        int i = idx / 20, k = idx % 20;
        sw1t[i][k] = (k < 19) ? w1[k * 19 + i] : 0.f;
    }
    for (int idx = tid; idx < 16 * 20; idx += 256) {
        int i = idx / 20, k = idx % 20;
        sw2t[i][k] = (k < 19) ? w2[k * 16 + i] : 0.f;
    }
    if (tid < 64) sw3t[tid / 16][tid % 16] = w3[(tid % 16) * 4 + tid / 16];
    __syncthreads();

    int warp = tid >> 5, lane = tid & 31;
    int b = blockIdx.x * 8 + warp;
    if (b >= B) return;
    float (*Sm)[20] = S[warp];

    const float* xb = x + (size_t)b * 361;
    for (int i = lane; i < 361; i += 32) Sm[i / 19][i % 19] = xb[i];
    if (lane < 20) Sm[lane][19] = 0.f;
    __syncwarp();

    float m[20];

    // ---- stage 1: M1 = w1^T X w1 (column `lane`) ----
    {
        float wc[20], t[20];
        int j = (lane < 19) ? lane : 0;
        #pragma unroll
        for (int k = 0; k < 19; ++k) wc[k] = sw1[k * 19 + j];
        wc[19] = 0.f;
        #pragma unroll
        for (int i = 0; i < 19; ++i) t[i] = dotv<5>(Sm[i], wc);
        t[19] = 0.f;
        #pragma unroll
        for (int i = 0; i < 19; ++i) {
            float acc = dotv<5>(sw1t[i], t);
            m[i] = (lane < 19) ? acc : 0.f;
        }
        m[19] = 0.f;
    }

    // ---- stage 2: ReEig(19x19) — Cholesky fast path ----
    if (!chol_test<19>(m, lane)) {
        float g[20], v[20];
        #pragma unroll
        for (int k = 0; k < 20; ++k) g[k] = m[k];
        jacobi_onesided<20>(g, v, lane, 12);
        reeig_correction<20, 19>(m, g, v, lane);
    }

    __syncwarp();
    if (lane < 19) {
        #pragma unroll
        for (int k = 0; k < 19; ++k) Sm[k][lane] = m[k];   // Y1
    }
    __syncwarp();

    // ---- stage 3: M2 = w2^T Y1 w2 (16x16) ----
    {
        float wc[20], t[20];
        int j = (lane < 16) ? lane : 0;
        #pragma unroll
        for (int k = 0; k < 19; ++k) wc[k] = sw2[k * 16 + j];
        wc[19] = 0.f;
        #pragma unroll
        for (int kk = 0; kk < 19; ++kk) t[kk] = dotv<5>(Sm[kk], wc);
        t[19] = 0.f;
        #pragma unroll
        for (int i = 0; i < 16; ++i) {
            float acc = dotv<5>(sw2t[i], t);
            m[i] = (lane < 16) ? acc : 0.f;
        }
        #pragma unroll
        for (int i = 16; i < 20; ++i) m[i] = 0.f;
    }

    // ---- stage 4: ReEig(16x16) — Cholesky fast path ----
    if (!chol_test<16>(m, lane)) {
        float g[20], v[20];
        #pragma unroll
        for (int k = 0; k < 20; ++k) g[k] = m[k];
        jacobi_onesided<16>(g, v, lane, 12);
        reeig_correction<16, 16>(m, g, v, lane);
    }

    __syncwarp();
    if (lane < 16) {
        #pragma unroll
        for (int k = 0; k < 16; ++k) Sm[k][lane] = m[k];   // Y2
    }
    __syncwarp();

    // ---- stage 5: M3 = w3^T Y2 w3 (4x4) ----
    float m4[4];
    {
        float wc[16], t[16];
        int j = (lane < 4) ? lane : 0;
        #pragma unroll
        for (int k = 0; k < 16; ++k) wc[k] = sw3[k * 4 + j];
        #pragma unroll
        for (int kk = 0; kk < 16; ++kk) t[kk] = dotv<4>(Sm[kk], wc);
        #pragma unroll
        for (int i = 0; i < 4; ++i) {
            float acc = dotv<4>(sw3t[i], t);
            m4[i] = (lane < 4) ? acc : 0.f;
        }
    }

    // ---- stage 6: LogEig(4x4) ----
    float g4[4], v4[4];
    #pragma unroll
    for (int k = 0; k < 4; ++k) g4[k] = m4[k];
    jacobi4(g4, v4, lane, 10);

    float lam = 0.f;
    #pragma unroll
    for (int k = 0; k < 4; ++k) lam = fmaf(v4[k], g4[k], lam);
    float ll = logf(fmaxf(lam, 1e-30f));

    float c3[4] = {0.f, 0.f, 0.f, 0.f};
    #pragma unroll
    for (int mm = 0; mm < 4; ++mm) {
        float llm = __shfl_sync(FULLMASK, ll,  mm);
        float bv0 = __shfl_sync(FULLMASK, v4[0], mm);
        float bv1 = __shfl_sync(FULLMASK, v4[1], mm);
        float bv2 = __shfl_sync(FULLMASK, v4[2], mm);
        float bv3 = __shfl_sync(FULLMASK, v4[3], mm);
        float vmj = (lane == 0) ? bv0 : (lane == 1) ? bv1 : (lane == 2) ? bv2 : bv3;
        float cf  = llm * vmj;
        c3[0] = fmaf(cf, bv0, c3[0]);
        c3[1] = fmaf(cf, bv1, c3[1]);
        c3[2] = fmaf(cf, bv2, c3[2]);
        c3[3] = fmaf(cf, bv3, c3[3]);
    }
    if (lane >= 4) { c3[0] = c3[1] = c3[2] = c3[3] = 0.f; }

    if (out_feat && lane < 4) {
        #pragma unroll
        for (int i = 0; i < 4; ++i)
            out_feat[(size_t)b * 16 + i * 4 + lane] = c3[i];
    }

    if (out_logp) {
        float p0 = 0.f, p1 = 0.f;
        int jj = (lane < 4) ? lane : 0;
        #pragma unroll
        for (int i = 0; i < 4; ++i) {
            int f = i * 4 + jj;
            p0 = fmaf(c3[i], sfc[f * 2 + 0], p0);
            p1 = fmaf(c3[i], sfc[f * 2 + 1], p1);
        }
        p0 += __shfl_xor_sync(FULLMASK, p0, 1);
        p0 += __shfl_xor_sync(FULLMASK, p0, 2);
        p1 += __shfl_xor_sync(FULLMASK, p1, 1);
        p1 += __shfl_xor_sync(FULLMASK, p1, 2);
        if (lane == 0) {
            float mx  = fmaxf(p0, p1);
            float lse = mx + logf(expf(p0 - mx) + expf(p1 - mx));
            out_logp[(size_t)b * 2 + 0] = p0 - lse;
            out_logp[(size_t)b * 2 + 1] = p1 - lse;
        }
    }
}

extern "C" void kernel_launch(void* const* d_in, const int* in_sizes, int n_in,
                              void* d_out, int out_size)
{
    const float* x   = (const float*)d_in[0];
    const float* w1  = (const float*)d_in[1];
    const float* w2  = (const float*)d_in[2];
    const float* w3  = (const float*)d_in[3];
    const float* fcw = (const float*)d_in[4];
    int B = in_sizes[0] / 361;

    float* out  = (float*)d_out;
    float* logp = nullptr;
    float* feat = nullptr;
    if (out_size == 18 * B)      { logp = out; feat = out + (size_t)2 * B; }
    else if (out_size == 2 * B)  { logp = out; }
    else if (out_size == 16 * B) { feat = out; }
    else                         { logp = out; feat = out + (size_t)2 * B; }

    int blocks = (B + 7) / 8;
    spd_net_kernel<<<blocks, 256>>>(x, w1, w2, w3, fcw, logp, feat, B);
}

// round 5
// speedup vs baseline: 1.6503x; 1.4455x over previous
#include <cuda_runtime.h>
#include <math.h>

#define FULLMASK 0xffffffffu
#define EPS_REC 1e-4f

// ---------------------------------------------------------------------------
// Full-warp Cholesky test on C = M - eps*I (one matrix/warp, lane j = col j).
// Warp-uniform result. Early break OK (uniform).
// ---------------------------------------------------------------------------
template<int NR>
__device__ __forceinline__ bool chol_test(const float (&m)[20], int lane)
{
    float c[NR];
    #pragma unroll
    for (int k = 0; k < NR; ++k) c[k] = (lane == k) ? (m[k] - EPS_REC) : m[k];

    bool ok = true;
    #pragma unroll
    for (int k = 0; k < NR; ++k) {
        float ckk = __shfl_sync(FULLMASK, c[k], k);
        if (ckk <= 1e-12f) { ok = false; break; }
        float inv  = __fdividef(1.0f, ckk);
        float gmul = c[k] * inv;
        #pragma unroll
        for (int i = k + 1; i < NR; ++i) {
            float pk = __shfl_sync(FULLMASK, c[i], k);
            c[i] = fmaf(-pk, gmul, c[i]);
        }
    }
    return ok;
}

// ---------------------------------------------------------------------------
// Grouped Cholesky test: two 16x16 matrices per warp (group g = lane>>4,
// column j = lane&15). No early break (groups may disagree); ok is sticky
// and group-uniform. NaN/Inf-safe: comparisons with NaN are false.
// ---------------------------------------------------------------------------
__device__ __forceinline__ bool chol16_grouped(const float (&m)[16], int lane)
{
    int base = lane & 16;
    int j    = lane & 15;
    float c[16];
    #pragma unroll
    for (int k = 0; k < 16; ++k) c[k] = (j == k) ? (m[k] - EPS_REC) : m[k];

    bool ok = true;
    #pragma unroll
    for (int k = 0; k < 16; ++k) {
        float ckk = __shfl_sync(FULLMASK, c[k], base + k);
        ok = ok && (ckk > 1e-12f);
        float inv  = __fdividef(1.0f, fmaxf(ckk, 1e-12f));
        float gmul = c[k] * inv;
        #pragma unroll
        for (int i = k + 1; i < 16; ++i) {
            float pk = __shfl_sync(FULLMASK, c[i], base + k);
            c[i] = fmaf(-pk, gmul, c[i]);
        }
    }
    return ok;
}

// ---------------------------------------------------------------------------
// Full-warp one-sided Jacobi — COLD fallback (noinline: contain registers).
// ---------------------------------------------------------------------------
template<int N>
__device__ __noinline__ void jacobi_onesided(float (&g)[20], float (&v)[20],
                                             int lane, int max_sweeps)
{
    constexpr int M = N - 1;
    #pragma unroll
    for (int k = 0; k < N; ++k) v[k] = (lane == k) ? 1.0f : 0.0f;

    for (int sweep = 0; sweep < max_sweeps; ++sweep) {
        bool anyrot = false;
        for (int r = 0; r < M; ++r) {
            int partner;
            if (lane >= N)      partner = lane;
            else if (lane == M) partner = r;
            else if (lane == r) partner = M;
            else                partner = ((2 * r - lane) % M + M) % M;

            float pg[N];
            float a0 = 0.f, a1 = 0.f, d0 = 0.f, d1 = 0.f;
            #pragma unroll
            for (int k = 0; k < N; ++k) {
                pg[k] = __shfl_sync(FULLMASK, g[k], partner);
                if (k & 1) { a1 = fmaf(g[k], g[k], a1); d1 = fmaf(g[k], pg[k], d1); }
                else       { a0 = fmaf(g[k], g[k], a0); d0 = fmaf(g[k], pg[k], d0); }
            }
            float a = a0 + a1;
            float d = d0 + d1;
            float bb = __shfl_sync(FULLMASK, a, partner);
            bool  lower = lane < partner;
            float app = lower ? a  : bb;
            float aqq = lower ? bb : a;

            bool rot = (d * d > 1e-12f * app * aqq);
            anyrot |= rot;

            float dsafe = rot ? d : 1.0f;
            float tau = __fdividef(aqq - app, 2.0f * dsafe);
            float t   = __fdividef(copysignf(1.0f, tau),
                                   fabsf(tau) + __fsqrt_rn(fmaf(tau, tau, 1.0f)));
            float cc  = __frsqrt_rn(fmaf(t, t, 1.0f));
            float ss  = t * cc;
            if (!rot) { cc = 1.0f; ss = 0.0f; }
            float sl = lower ? -ss : ss;

            #pragma unroll
            for (int k = 0; k < N; ++k) {
                float pv = __shfl_sync(FULLMASK, v[k], partner);
                g[k] = fmaf(sl, pg[k], cc * g[k]);
                v[k] = fmaf(sl, pv,    cc * v[k]);
            }
        }
        if (!__any_sync(FULLMASK, anyrot)) break;
    }
}

// ReEig correction (COLD): m += (eps - lambda_i) v_i v_i^T over deficient pairs.
template<int N, int NREAL>
__device__ __noinline__ void reeig_correction(float (&m)[20], const float (&g)[20],
                                              const float (&v)[20], int lane)
{
    float lam = 0.f;
    #pragma unroll
    for (int k = 0; k < N; ++k) lam = fmaf(v[k], g[k], lam);

    bool defic = (lane < NREAL) && (lam < EPS_REC);
    unsigned mask = __ballot_sync(FULLMASK, defic);
    while (mask) {
        int i = __ffs(mask) - 1;
        mask &= mask - 1;
        float li   = __shfl_sync(FULLMASK, lam, i);
        float coef = EPS_REC - li;
        float vmy  = 0.f;
        float bv[N];
        #pragma unroll
        for (int k = 0; k < N; ++k) {
            bv[k] = __shfl_sync(FULLMASK, v[k], i);
            vmy   = (lane == k) ? bv[k] : vmy;
        }
        float cf = coef * vmy;
        #pragma unroll
        for (int k = 0; k < N; ++k) m[k] = fmaf(cf, bv[k], m[k]);
    }
}

// ---------------------------------------------------------------------------
// Grouped 4x4 one-sided Jacobi: 4-lane groups (j = lane&3), replicated across
// the warp. HOT (LogEig).
// ---------------------------------------------------------------------------
__device__ __forceinline__ void jacobi4g(float (&g)[4], float (&v)[4],
                                         int lane, int max_sweeps)
{
    int j = lane & 3, base = lane & ~3;
    #pragma unroll
    for (int k = 0; k < 4; ++k) v[k] = (j == k) ? 1.0f : 0.0f;

    for (int sweep = 0; sweep < max_sweeps; ++sweep) {
        bool anyrot = false;
        #pragma unroll
        for (int r = 0; r < 3; ++r) {
            int p = (j == 3) ? r : (j == r) ? 3 : ((2 * r - j) % 3 + 3) % 3;
            int partner = base + p;

            float pg[4];
            float a = 0.f, d = 0.f;
            #pragma unroll
            for (int k = 0; k < 4; ++k) {
                pg[k] = __shfl_sync(FULLMASK, g[k], partner);
                a = fmaf(g[k], g[k], a);
                d = fmaf(g[k], pg[k], d);
            }
            float bb = __shfl_sync(FULLMASK, a, partner);
            bool  lower = j < p;
            float app = lower ? a  : bb;
            float aqq = lower ? bb : a;

            bool rot = (d * d > 1e-12f * app * aqq);
            anyrot |= rot;

            float dsafe = rot ? d : 1.0f;
            float tau = __fdividef(aqq - app, 2.0f * dsafe);
            float t   = __fdividef(copysignf(1.0f, tau),
                                   fabsf(tau) + __fsqrt_rn(fmaf(tau, tau, 1.0f)));
            float cc  = __frsqrt_rn(fmaf(t, t, 1.0f));
            float ss  = t * cc;
            if (!rot) { cc = 1.0f; ss = 0.0f; }
            float sl = lower ? -ss : ss;

            #pragma unroll
            for (int k = 0; k < 4; ++k) {
                float pv = __shfl_sync(FULLMASK, v[k], partner);
                g[k] = fmaf(sl, pg[k], cc * g[k]);
                v[k] = fmaf(sl, pv,    cc * v[k]);
            }
        }
        if (!__any_sync(FULLMASK, anyrot)) break;
    }
}

// Vectorized dot of a 16B-aligned shared row (Q float4s) with a register array.
template<int Q, int W>
__device__ __forceinline__ float dotv(const float* __restrict__ row,
                                      const float (&w)[W])
{
    const float4* r4 = (const float4*)row;
    float a0 = 0.f, a1 = 0.f, a2 = 0.f, a3 = 0.f;
    #pragma unroll
    for (int q = 0; q < Q; ++q) {
        float4 rv = r4[q];
        a0 = fmaf(rv.x, w[4 * q + 0], a0);
        a1 = fmaf(rv.y, w[4 * q + 1], a1);
        a2 = fmaf(rv.z, w[4 * q + 2], a2);
        a3 = fmaf(rv.w, w[4 * q + 3], a3);
    }
    return (a0 + a1) + (a2 + a3);
}

// ---------------------------------------------------------------------------
// 16 matrices per 256-thread block; each warp owns TWO matrices end-to-end.
// Stages 1-2: sequential per matrix (19 wide). Stages 3-4: two 16-lane
// groups. Stages 5-6: 4-lane groups (replicated). Matrix stride 420 floats
// (420 mod 32 = 4) -> the two groups' row reads hit disjoint banks.
// ---------------------------------------------------------------------------
__global__ void __launch_bounds__(256, 4)
spd_net_kernel(const float* __restrict__ x,
               const float* __restrict__ w1,
               const float* __restrict__ w2,
               const float* __restrict__ w3,
               const float* __restrict__ fcw,
               float* __restrict__ out_logp,
               float* __restrict__ out_feat,
               int B)
{
    __shared__ float sw1[361];                    // w1 row-major
    __shared__ float sw2[304];                    // w2 row-major
    __shared__ float sw3[64];                     // w3 row-major
    __shared__ __align__(16) float sw1t[19][20];  // w1^T padded
    __shared__ __align__(16) float sw2t[16][20];  // w2^T padded
    __shared__ __align__(16) float sw3t[4][16];   // w3^T
    __shared__ float sfc[32];
    __shared__ __align__(16) float S[16][21][20]; // 16 matrices, stride 420

    int tid = threadIdx.x;
    for (int i = tid; i < 361; i += 256) sw1[i] = w1[i];
    for (int i = tid; i < 304; i += 256) sw2[i] = w2[i];
    if (tid < 64) sw3[tid] = w3[tid];
    if (tid < 32) sfc[tid] = fcw[tid];
    for (int idx = tid; idx < 19 * 20; idx += 256) {
        int i = idx / 20, k = idx % 20;
        sw1t[i][k] = (k < 19) ? w1[k * 19 + i] : 0.f;
    }
    for (int idx = tid; idx < 16 * 20; idx += 256) {
        int i = idx / 20, k = idx % 20;
        sw2t[i][k] = (k < 19) ? w2[k * 16 + i] : 0.f;
    }
    if (tid < 64) sw3t[tid / 16][tid % 16] = w3[(tid % 16) * 4 + tid / 16];
    __syncthreads();

    int warp = tid >> 5, lane = tid & 31;
    int blockBase = blockIdx.x * 16;

    // ======================= Phase A: stages 1-2, x2 ========================
    #pragma unroll 1
    for (int r = 0; r < 2; ++r) {
        int q = 2 * warp + r;
        int b = blockBase + q;
        if (b >= B) continue;
        float (*Sm)[20] = S[q];

        const float* xb = x + (size_t)b * 361;
        for (int i = lane; i < 361; i += 32) Sm[i / 19][i % 19] = xb[i];
        if (lane < 20) Sm[lane][19] = 0.f;
        __syncwarp();

        float m[20];
        {
            float wc[20], t[20];
            int j = (lane < 19) ? lane : 0;
            #pragma unroll
            for (int k = 0; k < 19; ++k) wc[k] = sw1[k * 19 + j];
            wc[19] = 0.f;
            #pragma unroll
            for (int i = 0; i < 19; ++i) t[i] = dotv<5>(Sm[i], wc);
            t[19] = 0.f;
            #pragma unroll
            for (int i = 0; i < 19; ++i) {
                float acc = dotv<5>(sw1t[i], t);
                m[i] = (lane < 19) ? acc : 0.f;
            }
            m[19] = 0.f;
        }

        if (!chol_test<19>(m, lane)) {            // COLD
            float g[20], v[20];
            #pragma unroll
            for (int k = 0; k < 20; ++k) g[k] = m[k];
            jacobi_onesided<20>(g, v, lane, 12);
            reeig_correction<20, 19>(m, g, v, lane);
        }

        __syncwarp();
        if (lane < 19) {
            #pragma unroll
            for (int k = 0; k < 19; ++k) Sm[k][lane] = m[k];   // Y1
        }
        __syncwarp();
    }

    // ================= Phase B: stages 3-4, two 16-lane groups ==============
    int gB   = lane >> 4;            // 0 or 1
    int jB   = lane & 15;
    int qB   = 2 * warp + gB;
    float (*SmB)[20] = S[qB];

    float m16[16];
    {
        float wc[20], t[20];
        #pragma unroll
        for (int k = 0; k < 19; ++k) wc[k] = sw2[k * 16 + jB];
        wc[19] = 0.f;
        #pragma unroll
        for (int kk = 0; kk < 19; ++kk) t[kk] = dotv<5>(SmB[kk], wc);
        t[19] = 0.f;
        #pragma unroll
        for (int i = 0; i < 16; ++i) m16[i] = dotv<5>(sw2t[i], t);
    }

    bool okB = chol16_grouped(m16, lane);
    if (!__all_sync(FULLMASK, okB)) {             // COLD
        // park both matrices in shared, fix failing ones full-warp
        #pragma unroll
        for (int k = 0; k < 16; ++k) SmB[k][jB] = m16[k];
        __syncwarp();
        #pragma unroll 1
        for (int rr = 0; rr < 2; ++rr) {
            int qq = 2 * warp + rr;
            bool qok = __shfl_sync(FULLMASK, okB, rr * 16);
            if (!qok) {
                float mm[20], g[20], v[20];
                #pragma unroll
                for (int k = 0; k < 16; ++k)
                    mm[k] = (lane < 16) ? S[qq][k][lane] : 0.f;
                #pragma unroll
                for (int k = 16; k < 20; ++k) mm[k] = 0.f;
                if (lane >= 16) {
                    #pragma unroll
                    for (int k = 0; k < 16; ++k) mm[k] = 0.f;
                }
                #pragma unroll
                for (int k = 0; k < 20; ++k) g[k] = mm[k];
                jacobi_onesided<16>(g, v, lane, 12);
                reeig_correction<16, 16>(mm, g, v, lane);
                __syncwarp();
                if (lane < 16) {
                    #pragma unroll
                    for (int k = 0; k < 16; ++k) S[qq][k][lane] = mm[k];
                }
            }
            __syncwarp();
        }
        #pragma unroll
        for (int k = 0; k < 16; ++k) m16[k] = SmB[k][jB];
    }

    __syncwarp();
    #pragma unroll
    for (int k = 0; k < 16; ++k) SmB[k][jB] = m16[k];          // Y2
    __syncwarp();

    // ============ Phase C: stages 5-6, 4-lane groups (replicated) ===========
    int jC = lane & 3;
    int gC = (lane >> 2) & 1;        // which of the warp's two matrices
    int qC = 2 * warp + gC;
    int bC = blockBase + qC;
    float (*SmC)[20] = S[qC];

    float m4[4];
    {
        float wc[16], t[16];
        #pragma unroll
        for (int k = 0; k < 16; ++k) wc[k] = sw3[k * 4 + jC];
        #pragma unroll
        for (int kk = 0; kk < 16; ++kk) t[kk] = dotv<4>(SmC[kk], wc);
        #pragma unroll
        for (int i = 0; i < 4; ++i) m4[i] = dotv<4>(sw3t[i], t);
    }

    float g4[4], v4[4];
    #pragma unroll
    for (int k = 0; k < 4; ++k) g4[k] = m4[k];
    jacobi4g(g4, v4, lane, 10);

    float lam = 0.f;
    #pragma unroll
    for (int k = 0; k < 4; ++k) lam = fmaf(v4[k], g4[k], lam);
    float ll = logf(fmaxf(lam, 1e-30f));

    int baseC = lane & ~3;
    float c3[4] = {0.f, 0.f, 0.f, 0.f};
    #pragma unroll
    for (int mm = 0; mm < 4; ++mm) {
        float llm = __shfl_sync(FULLMASK, ll,    baseC + mm);
        float bv0 = __shfl_sync(FULLMASK, v4[0], baseC + mm);
        float bv1 = __shfl_sync(FULLMASK, v4[1], baseC + mm);
        float bv2 = __shfl_sync(FULLMASK, v4[2], baseC + mm);
        float bv3 = __shfl_sync(FULLMASK, v4[3], baseC + mm);
        float vmj = (jC == 0) ? bv0 : (jC == 1) ? bv1 : (jC == 2) ? bv2 : bv3;
        float cf  = llm * vmj;
        c3[0] = fmaf(cf, bv0, c3[0]);
        c3[1] = fmaf(cf, bv1, c3[1]);
        c3[2] = fmaf(cf, bv2, c3[2]);
        c3[3] = fmaf(cf, bv3, c3[3]);
    }

    bool writerLane = (lane < 8) && (bC < B);

    if (out_feat && writerLane) {
        #pragma unroll
        for (int i = 0; i < 4; ++i)
            out_feat[(size_t)bC * 16 + i * 4 + jC] = c3[i];
    }

    if (out_logp) {
        float p0 = 0.f, p1 = 0.f;
        #pragma unroll
        for (int i = 0; i < 4; ++i) {
            int f = i * 4 + jC;
            p0 = fmaf(c3[i], sfc[f * 2 + 0], p0);
            p1 = fmaf(c3[i], sfc[f * 2 + 1], p1);
        }
        p0 += __shfl_xor_sync(FULLMASK, p0, 1);
        p0 += __shfl_xor_sync(FULLMASK, p0, 2);
        p1 += __shfl_xor_sync(FULLMASK, p1, 1);
        p1 += __shfl_xor_sync(FULLMASK, p1, 2);
        if (writerLane && jC == 0) {
            float mx  = fmaxf(p0, p1);
            float lse = mx + logf(expf(p0 - mx) + expf(p1 - mx));
            out_logp[(size_t)bC * 2 + 0] = p0 - lse;
            out_logp[(size_t)bC * 2 + 1] = p1 - lse;
        }
    }
}

extern "C" void kernel_launch(void* const* d_in, const int* in_sizes, int n_in,
                              void* d_out, int out_size)
{
    const float* x   = (const float*)d_in[0];
    const float* w1  = (const float*)d_in[1];
    const float* w2  = (const float*)d_in[2];
    const float* w3  = (const float*)d_in[3];
    const float* fcw = (const float*)d_in[4];
    int B = in_sizes[0] / 361;

    float* out  = (float*)d_out;
    float* logp = nullptr;
    float* feat = nullptr;
    if (out_size == 18 * B)      { logp = out; feat = out + (size_t)2 * B; }
    else if (out_size == 2 * B)  { logp = out; }
    else if (out_size == 16 * B) { feat = out; }
    else                         { logp = out; feat = out + (size_t)2 * B; }

    int blocks = (B + 15) / 16;
    spd_net_kernel<<<blocks, 256>>>(x, w1, w2, w3, fcw, logp, feat, B);
}

// round 6
// speedup vs baseline: 1.7942x; 1.0872x over previous
#include <cuda_runtime.h>
#include <math.h>

#define FULLMASK 0xffffffffu
#define EPS_REC 1e-4f

// ---------------------------------------------------------------------------
// COLD one-sided Jacobi fallback (noinline to contain registers; spills OK).
// ---------------------------------------------------------------------------
template<int N>
__device__ __noinline__ void jacobi_onesided(float (&g)[20], float (&v)[20],
                                             int lane, int max_sweeps)
{
    constexpr int M = N - 1;
    #pragma unroll
    for (int k = 0; k < N; ++k) v[k] = (lane == k) ? 1.0f : 0.0f;

    for (int sweep = 0; sweep < max_sweeps; ++sweep) {
        bool anyrot = false;
        for (int r = 0; r < M; ++r) {
            int partner;
            if (lane >= N)      partner = lane;
            else if (lane == M) partner = r;
            else if (lane == r) partner = M;
            else                partner = ((2 * r - lane) % M + M) % M;

            float pg[N];
            float a0 = 0.f, a1 = 0.f, d0 = 0.f, d1 = 0.f;
            #pragma unroll
            for (int k = 0; k < N; ++k) {
                pg[k] = __shfl_sync(FULLMASK, g[k], partner);
                if (k & 1) { a1 = fmaf(g[k], g[k], a1); d1 = fmaf(g[k], pg[k], d1); }
                else       { a0 = fmaf(g[k], g[k], a0); d0 = fmaf(g[k], pg[k], d0); }
            }
            float a = a0 + a1;
            float d = d0 + d1;
            float bb = __shfl_sync(FULLMASK, a, partner);
            bool  lower = lane < partner;
            float app = lower ? a  : bb;
            float aqq = lower ? bb : a;

            bool rot = (d * d > 1e-12f * app * aqq);
            anyrot |= rot;

            float dsafe = rot ? d : 1.0f;
            float tau = __fdividef(aqq - app, 2.0f * dsafe);
            float t   = __fdividef(copysignf(1.0f, tau),
                                   fabsf(tau) + __fsqrt_rn(fmaf(tau, tau, 1.0f)));
            float cc  = __frsqrt_rn(fmaf(t, t, 1.0f));
            float ss  = t * cc;
            if (!rot) { cc = 1.0f; ss = 0.0f; }
            float sl = lower ? -ss : ss;

            #pragma unroll
            for (int k = 0; k < N; ++k) {
                float pv = __shfl_sync(FULLMASK, v[k], partner);
                g[k] = fmaf(sl, pg[k], cc * g[k]);
                v[k] = fmaf(sl, pv,    cc * v[k]);
            }
        }
        if (!__any_sync(FULLMASK, anyrot)) break;
    }
}

// COLD: m += (eps - lambda_i) v_i v_i^T over deficient eigenpairs.
template<int N, int NREAL>
__device__ __noinline__ void reeig_correction(float (&m)[20], const float (&g)[20],
                                              const float (&v)[20], int lane)
{
    float lam = 0.f;
    #pragma unroll
    for (int k = 0; k < N; ++k) lam = fmaf(v[k], g[k], lam);

    bool defic = (lane < NREAL) && (lam < EPS_REC);
    unsigned mask = __ballot_sync(FULLMASK, defic);
    while (mask) {
        int i = __ffs(mask) - 1;
        mask &= mask - 1;
        float li   = __shfl_sync(FULLMASK, lam, i);
        float coef = EPS_REC - li;
        float vmy  = 0.f;
        float bv[N];
        #pragma unroll
        for (int k = 0; k < N; ++k) {
            bv[k] = __shfl_sync(FULLMASK, v[k], i);
            vmy   = (lane == k) ? bv[k] : vmy;
        }
        float cf = coef * vmy;
        #pragma unroll
        for (int k = 0; k < N; ++k) m[k] = fmaf(cf, bv[k], m[k]);
    }
}

// ---------------------------------------------------------------------------
// Grouped Cholesky test: two 16x16 per warp (g = lane>>4, j = lane&15).
// Sticky ok, group-uniform, NaN-safe.
// ---------------------------------------------------------------------------
__device__ __forceinline__ bool chol16_grouped(const float (&m)[16], int lane)
{
    int base = lane & 16;
    int j    = lane & 15;
    float c[16];
    #pragma unroll
    for (int k = 0; k < 16; ++k) c[k] = (j == k) ? (m[k] - EPS_REC) : m[k];

    bool ok = true;
    #pragma unroll
    for (int k = 0; k < 16; ++k) {
        float ckk = __shfl_sync(FULLMASK, c[k], base + k);
        ok = ok && (ckk > 1e-12f);
        float gmul = c[k] * __fdividef(1.0f, fmaxf(ckk, 1e-12f));
        #pragma unroll
        for (int i = k + 1; i < 16; ++i) {
            float pk = __shfl_sync(FULLMASK, c[i], base + k);
            c[i] = fmaf(-pk, gmul, c[i]);
        }
    }
    return ok;
}

// Grouped 4x4 one-sided Jacobi (HOT, LogEig).
__device__ __forceinline__ void jacobi4g(float (&g)[4], float (&v)[4],
                                         int lane, int max_sweeps)
{
    int j = lane & 3, base = lane & ~3;
    #pragma unroll
    for (int k = 0; k < 4; ++k) v[k] = (j == k) ? 1.0f : 0.0f;

    for (int sweep = 0; sweep < max_sweeps; ++sweep) {
        bool anyrot = false;
        #pragma unroll
        for (int r = 0; r < 3; ++r) {
            int p = (j == 3) ? r : (j == r) ? 3 : ((2 * r - j) % 3 + 3) % 3;
            int partner = base + p;

            float pg[4];
            float a = 0.f, d = 0.f;
            #pragma unroll
            for (int k = 0; k < 4; ++k) {
                pg[k] = __shfl_sync(FULLMASK, g[k], partner);
                a = fmaf(g[k], g[k], a);
                d = fmaf(g[k], pg[k], d);
            }
            float bb = __shfl_sync(FULLMASK, a, partner);
            bool  lower = j < p;
            float app = lower ? a  : bb;
            float aqq = lower ? bb : a;

            bool rot = (d * d > 1e-12f * app * aqq);
            anyrot |= rot;

            float dsafe = rot ? d : 1.0f;
            float tau = __fdividef(aqq - app, 2.0f * dsafe);
            float t   = __fdividef(copysignf(1.0f, tau),
                                   fabsf(tau) + __fsqrt_rn(fmaf(tau, tau, 1.0f)));
            float cc  = __frsqrt_rn(fmaf(t, t, 1.0f));
            float ss  = t * cc;
            if (!rot) { cc = 1.0f; ss = 0.0f; }
            float sl = lower ? -ss : ss;

            #pragma unroll
            for (int k = 0; k < 4; ++k) {
                float pv = __shfl_sync(FULLMASK, v[k], partner);
                g[k] = fmaf(sl, pg[k], cc * g[k]);
                v[k] = fmaf(sl, pv,    cc * v[k]);
            }
        }
        if (!__any_sync(FULLMASK, anyrot)) break;
    }
}

// Vectorized dot of a 16B-aligned shared row (Q float4s) with a register array.
template<int Q, int W>
__device__ __forceinline__ float dotv(const float* __restrict__ row,
                                      const float (&w)[W])
{
    const float4* r4 = (const float4*)row;
    float a0 = 0.f, a1 = 0.f, a2 = 0.f, a3 = 0.f;
    #pragma unroll
    for (int q = 0; q < Q; ++q) {
        float4 rv = r4[q];
        a0 = fmaf(rv.x, w[4 * q + 0], a0);
        a1 = fmaf(rv.y, w[4 * q + 1], a1);
        a2 = fmaf(rv.z, w[4 * q + 2], a2);
        a3 = fmaf(rv.w, w[4 * q + 3], a3);
    }
    return (a0 + a1) + (a2 + a3);
}

// ---------------------------------------------------------------------------
// 16 matrices per 256-thread block, 2 per warp. Phase A fully fused across
// the pair: chunked first-half GEMM (wc as float4 chunks), weight-row-
// amortized second half streamed straight to shared, dual interleaved chol19.
// ---------------------------------------------------------------------------
__global__ void __launch_bounds__(256, 4)
spd_net_kernel(const float* __restrict__ x,
               const float* __restrict__ w1,
               const float* __restrict__ w2,
               const float* __restrict__ w3,
               const float* __restrict__ fcw,
               float* __restrict__ out_logp,
               float* __restrict__ out_feat,
               int B)
{
    __shared__ __align__(16) float sw1t[19][20];  // row i = column i of W1, pad 0
    __shared__ __align__(16) float sw2t[16][20];  // row i = column i of W2, pad 0
    __shared__ __align__(16) float sw3t[4][16];   // row i = column i of W3
    __shared__ float sfc[32];
    __shared__ __align__(16) float S[16][21][20]; // stride 420 floats/matrix

    int tid = threadIdx.x;
    for (int idx = tid; idx < 19 * 20; idx += 256) {
        int i = idx / 20, k = idx % 20;
        sw1t[i][k] = (k < 19) ? w1[k * 19 + i] : 0.f;
    }
    for (int idx = tid; idx < 16 * 20; idx += 256) {
        int i = idx / 20, k = idx % 20;
        sw2t[i][k] = (k < 19) ? w2[k * 16 + i] : 0.f;
    }
    if (tid < 64) sw3t[tid >> 4][tid & 15] = w3[(tid & 15) * 4 + (tid >> 4)];
    if (tid < 32) sfc[tid] = fcw[tid];
    __syncthreads();

    int warp = tid >> 5, lane = tid & 31;
    int blockBase = blockIdx.x * 16;
    int qA = 2 * warp, qBm = qA + 1;
    int bA = blockBase + qA, bB = blockBase + qBm;
    float (*SmA)[20] = S[qA];
    float (*SmB)[20] = S[qBm];

    // ---- load X for both matrices ----
    if (bA < B) {
        const float* xa = x + (size_t)bA * 361;
        for (int i = lane; i < 361; i += 32) SmA[i / 19][i % 19] = xa[i];
    }
    if (bB < B) {
        const float* xb = x + (size_t)bB * 361;
        for (int i = lane; i < 361; i += 32) SmB[i / 19][i % 19] = xb[i];
    }
    if (lane < 19) { SmA[lane][19] = 0.f; SmB[lane][19] = 0.f; }
    __syncwarp();

    int j19 = (lane < 19) ? lane : 0;

    // ======== Phase A: fused stage-1 GEMM for both matrices ========
    float tA[20], tB[20];
    #pragma unroll
    for (int i = 0; i < 20; ++i) { tA[i] = 0.f; tB[i] = 0.f; }

    #pragma unroll
    for (int q = 0; q < 5; ++q) {
        float4 wq = *(const float4*)&sw1t[j19][4 * q];   // wc chunk (col j of W1)
        #pragma unroll
        for (int i = 0; i < 19; ++i) {
            float4 ra = *(const float4*)&SmA[i][4 * q];
            float4 rb = *(const float4*)&SmB[i][4 * q];
            tA[i] = fmaf(ra.x, wq.x, fmaf(ra.y, wq.y, fmaf(ra.z, wq.z, fmaf(ra.w, wq.w, tA[i]))));
            tB[i] = fmaf(rb.x, wq.x, fmaf(rb.y, wq.y, fmaf(rb.z, wq.z, fmaf(rb.w, wq.w, tB[i]))));
        }
    }
    __syncwarp();   // all lanes done reading X before Y1 overwrites

    // second half: weight rows amortized over both matrices; stream to shared
    #pragma unroll
    for (int i = 0; i < 19; ++i) {
        float accA = dotv<5>(sw1t[i], tA);
        float accB = dotv<5>(sw1t[i], tB);
        if (lane < 19) { SmA[i][lane] = accA; SmB[i][lane] = accB; }  // Y1 = M1
    }
    __syncwarp();

    // ---- dual interleaved Cholesky test (19x19) ----
    float cA[19], cB[19];
    #pragma unroll
    for (int k = 0; k < 19; ++k) {
        float a = SmA[k][j19], b = SmB[k][j19];
        cA[k] = (j19 == k) ? a - EPS_REC : a;
        cB[k] = (j19 == k) ? b - EPS_REC : b;
    }
    bool okA = true, okB = true;
    #pragma unroll
    for (int k = 0; k < 19; ++k) {
        float pA = __shfl_sync(FULLMASK, cA[k], k);
        float pB = __shfl_sync(FULLMASK, cB[k], k);
        okA = okA && (pA > 1e-12f);
        okB = okB && (pB > 1e-12f);
        float gA = cA[k] * __fdividef(1.0f, fmaxf(pA, 1e-12f));
        float gB = cB[k] * __fdividef(1.0f, fmaxf(pB, 1e-12f));
        #pragma unroll
        for (int i = k + 1; i < 19; ++i) {
            float fA = __shfl_sync(FULLMASK, cA[i], k);
            float fB = __shfl_sync(FULLMASK, cB[i], k);
            cA[i] = fmaf(-fA, gA, cA[i]);
            cB[i] = fmaf(-fB, gB, cB[i]);
        }
    }

    if (!(okA && okB)) {                         // COLD
        #pragma unroll 1
        for (int rr = 0; rr < 2; ++rr) {
            bool ok = rr ? okB : okA;
            if (!ok) {
                float (*Sm)[20] = rr ? SmB : SmA;
                float m[20], g[20], v[20];
                #pragma unroll
                for (int k = 0; k < 19; ++k) m[k] = (lane < 19) ? Sm[k][lane] : 0.f;
                m[19] = 0.f;
                #pragma unroll
                for (int k = 0; k < 20; ++k) g[k] = m[k];
                jacobi_onesided<20>(g, v, lane, 12);
                reeig_correction<20, 19>(m, g, v, lane);
                __syncwarp();
                if (lane < 19) {
                    #pragma unroll
                    for (int k = 0; k < 19; ++k) Sm[k][lane] = m[k];
                }
            }
            __syncwarp();
        }
    }

    // ======== Phase B: stage 3-4, two 16-lane groups ========
    int gB2 = lane >> 4;
    int jB  = lane & 15;
    float (*SmP)[20] = S[2 * warp + gB2];

    float m16[16];
    {
        float wc[20], t[20];
        #pragma unroll
        for (int q = 0; q < 5; ++q)
            *(float4*)&wc[4 * q] = *(const float4*)&sw2t[jB][4 * q];
        #pragma unroll
        for (int kk = 0; kk < 19; ++kk) t[kk] = dotv<5>(SmP[kk], wc);
        t[19] = 0.f;
        #pragma unroll
        for (int i = 0; i < 16; ++i) m16[i] = dotv<5>(sw2t[i], t);
    }

    bool okP = chol16_grouped(m16, lane);
    if (!__all_sync(FULLMASK, okP)) {            // COLD
        #pragma unroll
        for (int k = 0; k < 16; ++k) SmP[k][jB] = m16[k];
        __syncwarp();
        #pragma unroll 1
        for (int rr = 0; rr < 2; ++rr) {
            int qq = 2 * warp + rr;
            bool qok = __shfl_sync(FULLMASK, okP, rr * 16);
            if (!qok) {
                float mm[20], g[20], v[20];
                #pragma unroll
                for (int k = 0; k < 16; ++k)
                    mm[k] = (lane < 16) ? S[qq][k][lane] : 0.f;
                #pragma unroll
                for (int k = 16; k < 20; ++k) mm[k] = 0.f;
                #pragma unroll
                for (int k = 0; k < 20; ++k) g[k] = mm[k];
                jacobi_onesided<16>(g, v, lane, 12);
                reeig_correction<16, 16>(mm, g, v, lane);
                __syncwarp();
                if (lane < 16) {
                    #pragma unroll
                    for (int k = 0; k < 16; ++k) S[qq][k][lane] = mm[k];
                }
            }
            __syncwarp();
        }
        #pragma unroll
        for (int k = 0; k < 16; ++k) m16[k] = SmP[k][jB];
    }

    __syncwarp();
    #pragma unroll
    for (int k = 0; k < 16; ++k) SmP[k][jB] = m16[k];          // Y2
    __syncwarp();

    // ======== Phase C: stage 5-6, 4-lane groups ========
    int jC = lane & 3;
    int gC = (lane >> 2) & 1;
    int qC = 2 * warp + gC;
    int bC = blockBase + qC;
    float (*SmC)[20] = S[qC];

    float m4[4];
    {
        float wc[16], t[16];
        #pragma unroll
        for (int q = 0; q < 4; ++q)
            *(float4*)&wc[4 * q] = *(const float4*)&sw3t[jC][4 * q];
        #pragma unroll
        for (int kk = 0; kk < 16; ++kk) t[kk] = dotv<4>(SmC[kk], wc);
        #pragma unroll
        for (int i = 0; i < 4; ++i) m4[i] = dotv<4>(sw3t[i], t);
    }

    float g4[4], v4[4];
    #pragma unroll
    for (int k = 0; k < 4; ++k) g4[k] = m4[k];
    jacobi4g(g4, v4, lane, 10);

    float lam = 0.f;
    #pragma unroll
    for (int k = 0; k < 4; ++k) lam = fmaf(v4[k], g4[k], lam);
    float ll = logf(fmaxf(lam, 1e-30f));

    int baseC = lane & ~3;
    float c3[4] = {0.f, 0.f, 0.f, 0.f};
    #pragma unroll
    for (int mm = 0; mm < 4; ++mm) {
        float llm = __shfl_sync(FULLMASK, ll,    baseC + mm);
        float bv0 = __shfl_sync(FULLMASK, v4[0], baseC + mm);
        float bv1 = __shfl_sync(FULLMASK, v4[1], baseC + mm);
        float bv2 = __shfl_sync(FULLMASK, v4[2], baseC + mm);
        float bv3 = __shfl_sync(FULLMASK, v4[3], baseC + mm);
        float vmj = (jC == 0) ? bv0 : (jC == 1) ? bv1 : (jC == 2) ? bv2 : bv3;
        float cf  = llm * vmj;
        c3[0] = fmaf(cf, bv0, c3[0]);
        c3[1] = fmaf(cf, bv1, c3[1]);
        c3[2] = fmaf(cf, bv2, c3[2]);
        c3[3] = fmaf(cf, bv3, c3[3]);
    }

    bool writerLane = (lane < 8) && (bC < B);

    if (out_feat && writerLane) {
        #pragma unroll
        for (int i = 0; i < 4; ++i)
            out_feat[(size_t)bC * 16 + i * 4 + jC] = c3[i];
    }

    if (out_logp) {
        float p0 = 0.f, p1 = 0.f;
        #pragma unroll
        for (int i = 0; i < 4; ++i) {
            int f = i * 4 + jC;
            p0 = fmaf(c3[i], sfc[f * 2 + 0], p0);
            p1 = fmaf(c3[i], sfc[f * 2 + 1], p1);
        }
        p0 += __shfl_xor_sync(FULLMASK, p0, 1);
        p0 += __shfl_xor_sync(FULLMASK, p0, 2);
        p1 += __shfl_xor_sync(FULLMASK, p1, 1);
        p1 += __shfl_xor_sync(FULLMASK, p1, 2);
        if (writerLane && jC == 0) {
            float mx  = fmaxf(p0, p1);
            float lse = mx + logf(expf(p0 - mx) + expf(p1 - mx));
            out_logp[(size_t)bC * 2 + 0] = p0 - lse;
            out_logp[(size_t)bC * 2 + 1] = p1 - lse;
        }
    }
}

extern "C" void kernel_launch(void* const* d_in, const int* in_sizes, int n_in,
                              void* d_out, int out_size)
{
    const float* x   = (const float*)d_in[0];
    const float* w1  = (const float*)d_in[1];
    const float* w2  = (const float*)d_in[2];
    const float* w3  = (const float*)d_in[3];
    const float* fcw = (const float*)d_in[4];
    int B = in_sizes[0] / 361;

    float* out  = (float*)d_out;
    float* logp = nullptr;
    float* feat = nullptr;
    if (out_size == 18 * B)      { logp = out; feat = out + (size_t)2 * B; }
    else if (out_size == 2 * B)  { logp = out; }
    else if (out_size == 16 * B) { feat = out; }
    else                         { logp = out; feat = out + (size_t)2 * B; }

    int blocks = (B + 15) / 16;
    spd_net_kernel<<<blocks, 256>>>(x, w1, w2, w3, fcw, logp, feat, B);
}